// round 6
// baseline (speedup 1.0000x reference)
#include <cuda_runtime.h>

// Problem dims
#define B_   4
#define N_   512
#define D_   512
#define H_   16
#define DH_  32
#define P_   64
#define FINAL_ELEMS (B_ * N_ * D_)      // final [B,N,D]; then attn [B,H,N,N]
#define RSQRT_DH 0.17677669529663687f   // 1/sqrt(32)

// Scratch (no cudaMalloc allowed)
__device__ __align__(16) float g_q[B_ * H_ * N_ * DH_];   // [B,H,N,DH]
__device__ __align__(16) float g_k[B_ * H_ * N_ * DH_];
__device__ __align__(16) float g_v[B_ * H_ * N_ * DH_];
__device__ __align__(16) float g_o[B_ * N_ * D_];         // [B,N,D] context before Wo

// Packed fp32x2 FMA (FFMA2) — doubles fp32 FMA throughput on sm_103a.
__device__ __forceinline__ float2 ffma2(float2 a, float2 b, float2 c) {
    float2 d;
    asm("fma.rn.f32x2 %0, %1, %2, %3;"
        : "=l"(reinterpret_cast<unsigned long long &>(d))
        : "l"(reinterpret_cast<unsigned long long &>(a)),
          "l"(reinterpret_cast<unsigned long long &>(b)),
          "l"(reinterpret_cast<unsigned long long &>(c)));
    return d;
}

// ===========================================================================
// GEMM core: 128x64 tile, 256 threads, 8x4 microtile, BK=16, double-buffered.
// As layout [k][row], row-pad 132 (multiple of 4 -> float4-aligned rows).
// ===========================================================================
#define APAD 132

// ---------------------------------------------------------------------------
// K1: QKV projection. C[2048,1536] = x[2048,512] @ [Wq|Wk|Wv], scattered into
// g_q/g_k/g_v with [B,H,N,DH] layout.
// ---------------------------------------------------------------------------
__global__ __launch_bounds__(256) void qkv_kernel(
    const float* __restrict__ x, const float* __restrict__ Wq,
    const float* __restrict__ Wk, const float* __restrict__ Wv) {
    __shared__ __align__(16) float As[2][16][APAD];
    __shared__ __align__(16) float Bs[2][16][64];

    int tid = threadIdx.x;
    int tx = tid & 15, ty = tid >> 4;       // 16 col-groups x 16 row-groups
    int row0 = blockIdx.y << 7;             // 128-row tile
    int col0 = blockIdx.x << 6;             // 64-col tile (global 0..1535)
    int mat = col0 >> 9;
    int wcol0 = col0 & 511;
    const float* W = (mat == 0) ? Wq : ((mat == 1) ? Wk : Wv);

    int arow = tid >> 2, akq = (tid & 3) << 2;   // A: 2 float4s (rows arow, arow+64)
    int brow = tid >> 4, bcol = (tid & 15) << 2; // B: 1 float4

    float2 acc[8][2];
#pragma unroll
    for (int i = 0; i < 8; i++) { acc[i][0] = make_float2(0.f, 0.f); acc[i][1] = make_float2(0.f, 0.f); }

    // load chunk 0
    {
        float4 a0 = *(const float4*)(x + (size_t)(row0 + arow) * 512 + akq);
        float4 a1 = *(const float4*)(x + (size_t)(row0 + arow + 64) * 512 + akq);
        As[0][akq + 0][arow] = a0.x; As[0][akq + 1][arow] = a0.y;
        As[0][akq + 2][arow] = a0.z; As[0][akq + 3][arow] = a0.w;
        As[0][akq + 0][arow + 64] = a1.x; As[0][akq + 1][arow + 64] = a1.y;
        As[0][akq + 2][arow + 64] = a1.z; As[0][akq + 3][arow + 64] = a1.w;
        *(float4*)&Bs[0][brow][bcol] = *(const float4*)(W + (size_t)brow * 512 + wcol0 + bcol);
    }
    __syncthreads();

    int buf = 0;
    for (int kk = 0; kk < 512; kk += 16) {
        float4 pa0, pa1, pb0;
        bool pf = (kk + 16) < 512;
        if (pf) {
            pa0 = *(const float4*)(x + (size_t)(row0 + arow) * 512 + kk + 16 + akq);
            pa1 = *(const float4*)(x + (size_t)(row0 + arow + 64) * 512 + kk + 16 + akq);
            pb0 = *(const float4*)(W + (size_t)(kk + 16 + brow) * 512 + wcol0 + bcol);
        }
#pragma unroll
        for (int k2 = 0; k2 < 16; k2++) {
            float4 a0 = *(float4*)&As[buf][k2][ty << 3];
            float4 a1 = *(float4*)&As[buf][k2][(ty << 3) + 4];
            float4 bv = *(float4*)&Bs[buf][k2][tx << 2];
            float2 b01 = make_float2(bv.x, bv.y);
            float2 b23 = make_float2(bv.z, bv.w);
            acc[0][0] = ffma2(make_float2(a0.x, a0.x), b01, acc[0][0]);
            acc[0][1] = ffma2(make_float2(a0.x, a0.x), b23, acc[0][1]);
            acc[1][0] = ffma2(make_float2(a0.y, a0.y), b01, acc[1][0]);
            acc[1][1] = ffma2(make_float2(a0.y, a0.y), b23, acc[1][1]);
            acc[2][0] = ffma2(make_float2(a0.z, a0.z), b01, acc[2][0]);
            acc[2][1] = ffma2(make_float2(a0.z, a0.z), b23, acc[2][1]);
            acc[3][0] = ffma2(make_float2(a0.w, a0.w), b01, acc[3][0]);
            acc[3][1] = ffma2(make_float2(a0.w, a0.w), b23, acc[3][1]);
            acc[4][0] = ffma2(make_float2(a1.x, a1.x), b01, acc[4][0]);
            acc[4][1] = ffma2(make_float2(a1.x, a1.x), b23, acc[4][1]);
            acc[5][0] = ffma2(make_float2(a1.y, a1.y), b01, acc[5][0]);
            acc[5][1] = ffma2(make_float2(a1.y, a1.y), b23, acc[5][1]);
            acc[6][0] = ffma2(make_float2(a1.z, a1.z), b01, acc[6][0]);
            acc[6][1] = ffma2(make_float2(a1.z, a1.z), b23, acc[6][1]);
            acc[7][0] = ffma2(make_float2(a1.w, a1.w), b01, acc[7][0]);
            acc[7][1] = ffma2(make_float2(a1.w, a1.w), b23, acc[7][1]);
        }
        if (pf) {
            int nb = buf ^ 1;
            As[nb][akq + 0][arow] = pa0.x; As[nb][akq + 1][arow] = pa0.y;
            As[nb][akq + 2][arow] = pa0.z; As[nb][akq + 3][arow] = pa0.w;
            As[nb][akq + 0][arow + 64] = pa1.x; As[nb][akq + 1][arow + 64] = pa1.y;
            As[nb][akq + 2][arow + 64] = pa1.z; As[nb][akq + 3][arow + 64] = pa1.w;
            *(float4*)&Bs[nb][brow][bcol] = pb0;
        }
        __syncthreads();
        buf ^= 1;
    }

    float* dst = (mat == 0) ? g_q : ((mat == 1) ? g_k : g_v);
    int c = wcol0 + (tx << 2);
    int h = c >> 5, dh = c & 31;
#pragma unroll
    for (int i = 0; i < 8; i++) {
        int r = row0 + (ty << 3) + i;
        int bb = r >> 9, n = r & 511;
        float4 v = make_float4(acc[i][0].x, acc[i][0].y, acc[i][1].x, acc[i][1].y);
        *(float4*)&dst[(((size_t)(bb * H_) + h) * N_ + n) * DH_ + dh] = v;
    }
}

// ---------------------------------------------------------------------------
// K2: fully fused bias + QK^T + softmax + AV.
// Block = (b, 4-query-row tile), ALL 16 heads, full m = 512. 512 threads.
// smem: scores[16][4][520], Ks/Vs[16][32][36], qs[16][4][32], Wps, mok.
// ---------------------------------------------------------------------------
#define SC_STRIDE 520
#define SC_H      2080                    // 4*520
#define KS_H      1152                    // 32*36
#define OFF_KS    33280                   // 16*4*520
#define OFF_QS    (OFF_KS + 18432)        // 16*32*36
#define OFF_WPS   (OFF_QS + 2048)
#define OFF_MOK   (OFF_WPS + 1024)
#define FUSED_SMEM_BYTES ((OFF_MOK + 512) * 4)   // 221184

__global__ __launch_bounds__(512, 1) void fused_attn_kernel(
    const float* __restrict__ pb, const float* __restrict__ Wp,
    const int* __restrict__ mask, float* __restrict__ attn) {
    extern __shared__ __align__(16) float sm[];
    float* scores = sm;             // [16][4][520]
    float* Ks     = sm + OFF_KS;    // [16][32][36]  (reused for V in phase 4)
    float* qs     = sm + OFF_QS;    // [16][4][32]
    float* Wps    = sm + OFF_WPS;   // [64][16]
    float* mok    = sm + OFF_MOK;   // [512]

    int tid = threadIdx.x;
    int b = blockIdx.y;
    int nb = blockIdx.x;            // 4-row tile index

    // ---- phase 0: loads ----
    {
        int h = tid >> 5, rem = tid & 31, n = rem >> 3, d4 = rem & 7;
        *(float4*)&qs[((h << 2) + n) * 32 + (d4 << 2)] =
            *(const float4*)(g_q + (((size_t)(b * H_ + h) * N_) + (nb << 2) + n) * DH_ + (d4 << 2));
    }
    if (tid < 256) ((float4*)Wps)[tid] = ((const float4*)Wp)[tid];
    mok[tid] = mask[(b << 9) + tid] ? 1.f : 0.f;
    __syncthreads();

    // ---- phase 1: pair bias -> scores smem ----
#pragma unroll
    for (int pi = 0; pi < 4; pi++) {
        int p = (pi << 9) + tid;
        int n = p >> 9, m = p & 511;
        float2 acc[8];
#pragma unroll
        for (int i = 0; i < 8; i++) acc[i] = make_float2(0.f, 0.f);
        if (mok[(nb << 2) + n] != 0.f && mok[m] != 0.f) {
            const float4* pbv = (const float4*)(pb +
                ((((size_t)b * N_ + (nb << 2) + n) * N_) + m) * P_);
#pragma unroll
            for (int p4 = 0; p4 < 16; p4++) {
                float4 v = pbv[p4];
                const float2* w = (const float2*)&Wps[(p4 << 2) * H_];
#pragma unroll
                for (int h2 = 0; h2 < 8; h2++) acc[h2] = ffma2(make_float2(v.x, v.x), w[h2],      acc[h2]);
#pragma unroll
                for (int h2 = 0; h2 < 8; h2++) acc[h2] = ffma2(make_float2(v.y, v.y), w[8 + h2],  acc[h2]);
#pragma unroll
                for (int h2 = 0; h2 < 8; h2++) acc[h2] = ffma2(make_float2(v.z, v.z), w[16 + h2], acc[h2]);
#pragma unroll
                for (int h2 = 0; h2 < 8; h2++) acc[h2] = ffma2(make_float2(v.w, v.w), w[24 + h2], acc[h2]);
            }
        }
        int base = n * SC_STRIDE + m;
#pragma unroll
        for (int h = 0; h < 16; h++)
            scores[h * SC_H + base] = (h & 1) ? acc[h >> 1].y : acc[h >> 1].x;
    }
    __syncthreads();

    // per-warp mapping for phases 2 & 4: warp = head
    int h  = tid >> 5;
    int n  = (tid >> 3) & 3;
    int mg = tid & 7;

    // ---- phase 2: scores += q.k / sqrt(DH), K streamed in 32-m chunks ----
    float2 q2[16];
#pragma unroll
    for (int t = 0; t < 16; t++) q2[t] = *(float2*)&qs[((h << 2) + n) * 32 + (t << 1)];

    for (int mc = 0; mc < 512; mc += 32) {
#pragma unroll
        for (int j = 0; j < 8; j++) {
            int f = tid + (j << 9);
            int hl = f >> 8, rem = f & 255, ml = rem >> 3, d4 = rem & 7;
            *(float4*)&Ks[hl * KS_H + ml * 36 + (d4 << 2)] =
                *(const float4*)(g_k + (((size_t)(b * H_ + hl) * N_) + mc + ml) * DH_ + (d4 << 2));
        }
        __syncthreads();
#pragma unroll
        for (int i = 0; i < 4; i++) {
            int ml = mg + (i << 3);
            const float* kr = &Ks[h * KS_H + ml * 36];
            float2 a = make_float2(0.f, 0.f);
#pragma unroll
            for (int d4 = 0; d4 < 8; d4++) {
                float4 k4 = *(const float4*)&kr[d4 << 2];
                a = ffma2(q2[2 * d4],     make_float2(k4.x, k4.y), a);
                a = ffma2(q2[2 * d4 + 1], make_float2(k4.z, k4.w), a);
            }
            int sidx = ((h << 2) + n) * SC_STRIDE + mc + ml;
            scores[sidx] += (a.x + a.y) * RSQRT_DH;
        }
        __syncthreads();
    }

    // ---- phase 3: key-mask + softmax per (h,n) row; write attn; p -> smem ----
    {
        int w = tid >> 5, lane = tid & 31;
#pragma unroll
        for (int j = 0; j < 4; j++) {
            int row = (w << 2) + j;
            int h3 = row >> 2, n3 = row & 3;
            float* srow = &scores[((h3 << 2) + n3) * SC_STRIDE];
            float s[16];
            float mx = -3.0e38f;
#pragma unroll
            for (int i = 0; i < 16; i++) {
                int m = lane + (i << 5);
                float v = srow[m];
                v = (mok[m] != 0.f) ? v : -1e6f;
                s[i] = v;
                mx = fmaxf(mx, v);
            }
#pragma unroll
            for (int o = 16; o > 0; o >>= 1) mx = fmaxf(mx, __shfl_xor_sync(0xffffffffu, mx, o));
            float sum = 0.f;
#pragma unroll
            for (int i = 0; i < 16; i++) { s[i] = __expf(s[i] - mx); sum += s[i]; }
#pragma unroll
            for (int o = 16; o > 0; o >>= 1) sum += __shfl_xor_sync(0xffffffffu, sum, o);
            float inv = 1.0f / sum;
            size_t abase = (((size_t)(b * H_ + h3) * N_) + (nb << 2) + n3) * N_;
#pragma unroll
            for (int i = 0; i < 16; i++) {
                float pv = s[i] * inv;
                srow[lane + (i << 5)] = pv;
                attn[abase + lane + (i << 5)] = pv;
            }
        }
    }
    __syncthreads();

    // ---- phase 4: out = P @ V, V streamed in 32-m chunks (reuse Ks) ----
    float2 o01 = make_float2(0.f, 0.f), o23 = make_float2(0.f, 0.f);
    for (int mc = 0; mc < 512; mc += 32) {
#pragma unroll
        for (int j = 0; j < 8; j++) {
            int f = tid + (j << 9);
            int hl = f >> 8, rem = f & 255, ml = rem >> 3, d4 = rem & 7;
            *(float4*)&Ks[hl * KS_H + ml * 36 + (d4 << 2)] =
                *(const float4*)(g_v + (((size_t)(b * H_ + hl) * N_) + mc + ml) * DH_ + (d4 << 2));
        }
        __syncthreads();
        const float* prow = &scores[((h << 2) + n) * SC_STRIDE + mc];
#pragma unroll
        for (int ii = 0; ii < 8; ii++) {
            float4 p4 = *(const float4*)&prow[ii << 2];
            const float* vb = &Ks[h * KS_H + (ii << 2) * 36 + (mg << 2)];
            float4 v0 = *(const float4*)&vb[0];
            float4 v1 = *(const float4*)&vb[36];
            float4 v2 = *(const float4*)&vb[72];
            float4 v3 = *(const float4*)&vb[108];
            o01 = ffma2(make_float2(p4.x, p4.x), make_float2(v0.x, v0.y), o01);
            o23 = ffma2(make_float2(p4.x, p4.x), make_float2(v0.z, v0.w), o23);
            o01 = ffma2(make_float2(p4.y, p4.y), make_float2(v1.x, v1.y), o01);
            o23 = ffma2(make_float2(p4.y, p4.y), make_float2(v1.z, v1.w), o23);
            o01 = ffma2(make_float2(p4.z, p4.z), make_float2(v2.x, v2.y), o01);
            o23 = ffma2(make_float2(p4.z, p4.z), make_float2(v2.z, v2.w), o23);
            o01 = ffma2(make_float2(p4.w, p4.w), make_float2(v3.x, v3.y), o01);
            o23 = ffma2(make_float2(p4.w, p4.w), make_float2(v3.z, v3.w), o23);
        }
        __syncthreads();
    }
    *(float4*)&g_o[(((size_t)b * N_) + (nb << 2) + n) * D_ + (h << 5) + (mg << 2)] =
        make_float4(o01.x, o01.y, o23.x, o23.y);
}

// ---------------------------------------------------------------------------
// K3: final = (g_o @ Wo), zero masked query rows. Same 128x64 GEMM core.
// ---------------------------------------------------------------------------
__global__ __launch_bounds__(256) void outproj_kernel(
    const float* __restrict__ Wo, const int* __restrict__ mask,
    float* __restrict__ outp) {
    __shared__ __align__(16) float As[2][16][APAD];
    __shared__ __align__(16) float Bs[2][16][64];

    int tid = threadIdx.x;
    int tx = tid & 15, ty = tid >> 4;
    int row0 = blockIdx.y << 7;
    int col0 = blockIdx.x << 6;

    int arow = tid >> 2, akq = (tid & 3) << 2;
    int brow = tid >> 4, bcol = (tid & 15) << 2;

    float2 acc[8][2];
#pragma unroll
    for (int i = 0; i < 8; i++) { acc[i][0] = make_float2(0.f, 0.f); acc[i][1] = make_float2(0.f, 0.f); }

    {
        float4 a0 = *(const float4*)(g_o + (size_t)(row0 + arow) * 512 + akq);
        float4 a1 = *(const float4*)(g_o + (size_t)(row0 + arow + 64) * 512 + akq);
        As[0][akq + 0][arow] = a0.x; As[0][akq + 1][arow] = a0.y;
        As[0][akq + 2][arow] = a0.z; As[0][akq + 3][arow] = a0.w;
        As[0][akq + 0][arow + 64] = a1.x; As[0][akq + 1][arow + 64] = a1.y;
        As[0][akq + 2][arow + 64] = a1.z; As[0][akq + 3][arow + 64] = a1.w;
        *(float4*)&Bs[0][brow][bcol] = *(const float4*)(Wo + (size_t)brow * 512 + col0 + bcol);
    }
    __syncthreads();

    int buf = 0;
    for (int kk = 0; kk < 512; kk += 16) {
        float4 pa0, pa1, pb0;
        bool pf = (kk + 16) < 512;
        if (pf) {
            pa0 = *(const float4*)(g_o + (size_t)(row0 + arow) * 512 + kk + 16 + akq);
            pa1 = *(const float4*)(g_o + (size_t)(row0 + arow + 64) * 512 + kk + 16 + akq);
            pb0 = *(const float4*)(Wo + (size_t)(kk + 16 + brow) * 512 + col0 + bcol);
        }
#pragma unroll
        for (int k2 = 0; k2 < 16; k2++) {
            float4 a0 = *(float4*)&As[buf][k2][ty << 3];
            float4 a1 = *(float4*)&As[buf][k2][(ty << 3) + 4];
            float4 bv = *(float4*)&Bs[buf][k2][tx << 2];
            float2 b01 = make_float2(bv.x, bv.y);
            float2 b23 = make_float2(bv.z, bv.w);
            acc[0][0] = ffma2(make_float2(a0.x, a0.x), b01, acc[0][0]);
            acc[0][1] = ffma2(make_float2(a0.x, a0.x), b23, acc[0][1]);
            acc[1][0] = ffma2(make_float2(a0.y, a0.y), b01, acc[1][0]);
            acc[1][1] = ffma2(make_float2(a0.y, a0.y), b23, acc[1][1]);
            acc[2][0] = ffma2(make_float2(a0.z, a0.z), b01, acc[2][0]);
            acc[2][1] = ffma2(make_float2(a0.z, a0.z), b23, acc[2][1]);
            acc[3][0] = ffma2(make_float2(a0.w, a0.w), b01, acc[3][0]);
            acc[3][1] = ffma2(make_float2(a0.w, a0.w), b23, acc[3][1]);
            acc[4][0] = ffma2(make_float2(a1.x, a1.x), b01, acc[4][0]);
            acc[4][1] = ffma2(make_float2(a1.x, a1.x), b23, acc[4][1]);
            acc[5][0] = ffma2(make_float2(a1.y, a1.y), b01, acc[5][0]);
            acc[5][1] = ffma2(make_float2(a1.y, a1.y), b23, acc[5][1]);
            acc[6][0] = ffma2(make_float2(a1.z, a1.z), b01, acc[6][0]);
            acc[6][1] = ffma2(make_float2(a1.z, a1.z), b23, acc[6][1]);
            acc[7][0] = ffma2(make_float2(a1.w, a1.w), b01, acc[7][0]);
            acc[7][1] = ffma2(make_float2(a1.w, a1.w), b23, acc[7][1]);
        }
        if (pf) {
            int nb = buf ^ 1;
            As[nb][akq + 0][arow] = pa0.x; As[nb][akq + 1][arow] = pa0.y;
            As[nb][akq + 2][arow] = pa0.z; As[nb][akq + 3][arow] = pa0.w;
            As[nb][akq + 0][arow + 64] = pa1.x; As[nb][akq + 1][arow + 64] = pa1.y;
            As[nb][akq + 2][arow + 64] = pa1.z; As[nb][akq + 3][arow + 64] = pa1.w;
            *(float4*)&Bs[nb][brow][bcol] = pb0;
        }
        __syncthreads();
        buf ^= 1;
    }

    int c = col0 + (tx << 2);
#pragma unroll
    for (int i = 0; i < 8; i++) {
        int r = row0 + (ty << 3) + i;
        float msk = mask[r] ? 1.f : 0.f;
        float4 v = make_float4(acc[i][0].x * msk, acc[i][0].y * msk,
                               acc[i][1].x * msk, acc[i][1].y * msk);
        *(float4*)&outp[(size_t)r * 512 + c] = v;
    }
}

// ---------------------------------------------------------------------------
extern "C" void kernel_launch(void* const* d_in, const int* in_sizes, int n_in,
                              void* d_out, int out_size) {
    const float* x    = (const float*)d_in[0];
    const float* pb   = (const float*)d_in[1];
    const float* Wq   = (const float*)d_in[2];
    const float* Wk   = (const float*)d_in[3];
    const float* Wv   = (const float*)d_in[4];
    const float* Wo   = (const float*)d_in[5];
    const float* Wp   = (const float*)d_in[6];
    const int*   mask = (const int*)d_in[7];

    float* out  = (float*)d_out;
    float* attn = out + FINAL_ELEMS;

    static int inited = 0;
    if (!inited) {
        cudaFuncSetAttribute(fused_attn_kernel,
                             cudaFuncAttributeMaxDynamicSharedMemorySize,
                             FUSED_SMEM_BYTES);
        inited = 1;
    }

    qkv_kernel<<<dim3(24, 16), 256>>>(x, Wq, Wk, Wv);
    fused_attn_kernel<<<dim3(128, 4), 512, FUSED_SMEM_BYTES>>>(pb, Wp, mask, attn);
    outproj_kernel<<<dim3(8, 16), 256>>>(Wo, mask, out);
}

// round 7
// speedup vs baseline: 1.3006x; 1.3006x over previous
#include <cuda_runtime.h>

// Problem dims
#define B_   4
#define N_   512
#define D_   512
#define H_   16
#define DH_  32
#define P_   64
#define FINAL_ELEMS (B_ * N_ * D_)      // final [B,N,D]; then attn [B,H,N,N]
#define RSQRT_DH 0.17677669529663687f   // 1/sqrt(32)

// Scratch (no cudaMalloc allowed)
__device__ __align__(16) float g_q[B_ * H_ * N_ * DH_];   // [B,H,N,DH]
__device__ __align__(16) float g_k[B_ * H_ * N_ * DH_];
__device__ __align__(16) float g_v[B_ * H_ * N_ * DH_];
__device__ __align__(16) float g_o[B_ * N_ * D_];         // [B,N,D] context before Wo

// Packed fp32x2 FMA (FFMA2) — doubles fp32 FMA throughput on sm_103a.
__device__ __forceinline__ float2 ffma2(float2 a, float2 b, float2 c) {
    float2 d;
    asm("fma.rn.f32x2 %0, %1, %2, %3;"
        : "=l"(reinterpret_cast<unsigned long long &>(d))
        : "l"(reinterpret_cast<unsigned long long &>(a)),
          "l"(reinterpret_cast<unsigned long long &>(b)),
          "l"(reinterpret_cast<unsigned long long &>(c)));
    return d;
}

// ===========================================================================
// GEMM core: 128x64 tile, 256 threads, 8x4 microtile, BK=16, double-buffered.
// As layout [k][row], row-pad 132 (multiple of 4 -> float4-aligned rows).
// ===========================================================================
#define APAD 132

// ---------------------------------------------------------------------------
// K1: QKV projection. C[2048,1536] = x[2048,512] @ [Wq|Wk|Wv], scattered into
// g_q/g_k/g_v with [B,H,N,DH] layout.
// ---------------------------------------------------------------------------
__global__ __launch_bounds__(256) void qkv_kernel(
    const float* __restrict__ x, const float* __restrict__ Wq,
    const float* __restrict__ Wk, const float* __restrict__ Wv) {
    __shared__ __align__(16) float As[2][16][APAD];
    __shared__ __align__(16) float Bs[2][16][64];

    int tid = threadIdx.x;
    int tx = tid & 15, ty = tid >> 4;
    int row0 = blockIdx.y << 7;
    int col0 = blockIdx.x << 6;
    int mat = col0 >> 9;
    int wcol0 = col0 & 511;
    const float* W = (mat == 0) ? Wq : ((mat == 1) ? Wk : Wv);

    int arow = tid >> 2, akq = (tid & 3) << 2;
    int brow = tid >> 4, bcol = (tid & 15) << 2;

    float2 acc[8][2];
#pragma unroll
    for (int i = 0; i < 8; i++) { acc[i][0] = make_float2(0.f, 0.f); acc[i][1] = make_float2(0.f, 0.f); }

    {
        float4 a0 = *(const float4*)(x + (size_t)(row0 + arow) * 512 + akq);
        float4 a1 = *(const float4*)(x + (size_t)(row0 + arow + 64) * 512 + akq);
        As[0][akq + 0][arow] = a0.x; As[0][akq + 1][arow] = a0.y;
        As[0][akq + 2][arow] = a0.z; As[0][akq + 3][arow] = a0.w;
        As[0][akq + 0][arow + 64] = a1.x; As[0][akq + 1][arow + 64] = a1.y;
        As[0][akq + 2][arow + 64] = a1.z; As[0][akq + 3][arow + 64] = a1.w;
        *(float4*)&Bs[0][brow][bcol] = *(const float4*)(W + (size_t)brow * 512 + wcol0 + bcol);
    }
    __syncthreads();

    int buf = 0;
    for (int kk = 0; kk < 512; kk += 16) {
        float4 pa0, pa1, pb0;
        bool pf = (kk + 16) < 512;
        if (pf) {
            pa0 = *(const float4*)(x + (size_t)(row0 + arow) * 512 + kk + 16 + akq);
            pa1 = *(const float4*)(x + (size_t)(row0 + arow + 64) * 512 + kk + 16 + akq);
            pb0 = *(const float4*)(W + (size_t)(kk + 16 + brow) * 512 + wcol0 + bcol);
        }
#pragma unroll
        for (int k2 = 0; k2 < 16; k2++) {
            float4 a0 = *(float4*)&As[buf][k2][ty << 3];
            float4 a1 = *(float4*)&As[buf][k2][(ty << 3) + 4];
            float4 bv = *(float4*)&Bs[buf][k2][tx << 2];
            float2 b01 = make_float2(bv.x, bv.y);
            float2 b23 = make_float2(bv.z, bv.w);
            acc[0][0] = ffma2(make_float2(a0.x, a0.x), b01, acc[0][0]);
            acc[0][1] = ffma2(make_float2(a0.x, a0.x), b23, acc[0][1]);
            acc[1][0] = ffma2(make_float2(a0.y, a0.y), b01, acc[1][0]);
            acc[1][1] = ffma2(make_float2(a0.y, a0.y), b23, acc[1][1]);
            acc[2][0] = ffma2(make_float2(a0.z, a0.z), b01, acc[2][0]);
            acc[2][1] = ffma2(make_float2(a0.z, a0.z), b23, acc[2][1]);
            acc[3][0] = ffma2(make_float2(a0.w, a0.w), b01, acc[3][0]);
            acc[3][1] = ffma2(make_float2(a0.w, a0.w), b23, acc[3][1]);
            acc[4][0] = ffma2(make_float2(a1.x, a1.x), b01, acc[4][0]);
            acc[4][1] = ffma2(make_float2(a1.x, a1.x), b23, acc[4][1]);
            acc[5][0] = ffma2(make_float2(a1.y, a1.y), b01, acc[5][0]);
            acc[5][1] = ffma2(make_float2(a1.y, a1.y), b23, acc[5][1]);
            acc[6][0] = ffma2(make_float2(a1.z, a1.z), b01, acc[6][0]);
            acc[6][1] = ffma2(make_float2(a1.z, a1.z), b23, acc[6][1]);
            acc[7][0] = ffma2(make_float2(a1.w, a1.w), b01, acc[7][0]);
            acc[7][1] = ffma2(make_float2(a1.w, a1.w), b23, acc[7][1]);
        }
        if (pf) {
            int nb = buf ^ 1;
            As[nb][akq + 0][arow] = pa0.x; As[nb][akq + 1][arow] = pa0.y;
            As[nb][akq + 2][arow] = pa0.z; As[nb][akq + 3][arow] = pa0.w;
            As[nb][akq + 0][arow + 64] = pa1.x; As[nb][akq + 1][arow + 64] = pa1.y;
            As[nb][akq + 2][arow + 64] = pa1.z; As[nb][akq + 3][arow + 64] = pa1.w;
            *(float4*)&Bs[nb][brow][bcol] = pb0;
        }
        __syncthreads();
        buf ^= 1;
    }

    float* dst = (mat == 0) ? g_q : ((mat == 1) ? g_k : g_v);
    int c = wcol0 + (tx << 2);
    int h = c >> 5, dh = c & 31;
#pragma unroll
    for (int i = 0; i < 8; i++) {
        int r = row0 + (ty << 3) + i;
        int bb = r >> 9, n = r & 511;
        float4 v = make_float4(acc[i][0].x, acc[i][0].y, acc[i][1].x, acc[i][1].y);
        *(float4*)&dst[(((size_t)(bb * H_) + h) * N_ + n) * DH_ + dh] = v;
    }
}

// ---------------------------------------------------------------------------
// K2: bias[b,h,n,m] = pair_mask ? sum_p pair_bias[b,n,m,p]*Wp[p,h] : 0
// written into d_out attn region. Skips pair_bias read when masked (~75%).
// One block per (b,n); 256 threads, 2 m's each.
// ---------------------------------------------------------------------------
__global__ __launch_bounds__(256) void bias_kernel(
    const float* __restrict__ pb, const float* __restrict__ Wp,
    const int* __restrict__ mask, float* __restrict__ attn) {
    __shared__ __align__(16) float Wps[P_ * H_];   // [p][h]
    int tid = threadIdx.x;
    Wps[tid] = Wp[tid];
    Wps[tid + 256] = Wp[tid + 256];
    Wps[tid + 512] = Wp[tid + 512];
    Wps[tid + 768] = Wp[tid + 768];
    __syncthreads();

    int bn = blockIdx.x;
    int bb = bn >> 9, n = bn & 511;
    int mn = mask[bn];

#pragma unroll
    for (int mi = 0; mi < 2; mi++) {
        int m = tid + (mi << 8);
        float2 acc[8];
#pragma unroll
        for (int i = 0; i < 8; i++) acc[i] = make_float2(0.f, 0.f);
        if (mn && mask[(bb << 9) + m]) {
            const float4* pbv = (const float4*)(pb + (((size_t)bn) * N_ + m) * P_);
#pragma unroll
            for (int p4 = 0; p4 < 16; p4++) {
                float4 v = pbv[p4];
                const float2* w = (const float2*)&Wps[(p4 * 4) * H_];
#pragma unroll
                for (int h2 = 0; h2 < 8; h2++) acc[h2] = ffma2(make_float2(v.x, v.x), w[h2],      acc[h2]);
#pragma unroll
                for (int h2 = 0; h2 < 8; h2++) acc[h2] = ffma2(make_float2(v.y, v.y), w[8 + h2],  acc[h2]);
#pragma unroll
                for (int h2 = 0; h2 < 8; h2++) acc[h2] = ffma2(make_float2(v.z, v.z), w[16 + h2], acc[h2]);
#pragma unroll
                for (int h2 = 0; h2 < 8; h2++) acc[h2] = ffma2(make_float2(v.w, v.w), w[24 + h2], acc[h2]);
            }
        }
        size_t base = (((size_t)bb * H_) * N_ + n) * N_ + m;
#pragma unroll
        for (int h = 0; h < H_; h++) {
            float val = (h & 1) ? acc[h >> 1].y : acc[h >> 1].x;
            attn[base + (size_t)h * (N_ * N_)] = val;
        }
    }
}

// ---------------------------------------------------------------------------
// K3: fused attention per (b,h, 16-row tile): scores = qK^T/sqrt(DH) + bias,
// key mask, softmax -> attn (d_out), probs staged in smem, then P @ V -> g_o
// with (row, d-pair) ownership (no shuffle reduction epilogue).
// K/V head resident in smem (stride 36, conflict-free float4).
// 256 threads = 16 rows x 16 col-groups.
// ---------------------------------------------------------------------------
#define PS_STRIDE 520
#define K3_SMEM_FLOATS (512 * 36 * 2 + 16 * PS_STRIDE + 512 + 512)
#define K3_SMEM_BYTES  (K3_SMEM_FLOATS * 4)   // 184320 B

__global__ __launch_bounds__(256, 1) void attn_kernel(
    const int* __restrict__ mask, float* __restrict__ attn) {
    extern __shared__ __align__(16) float sm[];
    float* Ks  = sm;                       // [512][36]
    float* Vs  = Ks + 512 * 36;            // [512][36]
    float* Ps  = Vs + 512 * 36;            // [16][520] probs
    float* qs  = Ps + 16 * PS_STRIDE;      // [16][32]
    float* mok = qs + 512;                 // [512]

    int tid = threadIdx.x;
    int bh = blockIdx.y;              // b*H + h
    int bb = bh >> 4;
    int n0 = blockIdx.x << 4;

    const float* gk = g_k + (size_t)bh * (N_ * DH_);
    const float* gv = g_v + (size_t)bh * (N_ * DH_);
    const float* gq = g_q + (size_t)bh * (N_ * DH_);

#pragma unroll
    for (int j = 0; j < 16; j++) {
        int i4 = tid + (j << 8);                // 0..4095 float4s
        int m = i4 >> 3, kq = (i4 & 7) << 2;
        *(float4*)&Ks[m * 36 + kq] = *(const float4*)(gk + ((size_t)i4 << 2));
        *(float4*)&Vs[m * 36 + kq] = *(const float4*)(gv + ((size_t)i4 << 2));
    }
    if (tid < 128)
        *(float4*)&qs[tid << 2] = *(const float4*)(gq + (size_t)n0 * DH_ + (tid << 2));
    mok[tid]       = mask[(bb << 9) + tid]       ? 1.f : 0.f;
    mok[tid + 256] = mask[(bb << 9) + tid + 256] ? 1.f : 0.f;
    __syncthreads();

    int row = tid >> 4, cg = tid & 15;
    int n = n0 + row;

    float2 q2[16];
#pragma unroll
    for (int t = 0; t < 16; t++) q2[t] = *(float2*)&qs[(row << 5) + (t << 1)];

    // scores: thread owns m = j*16 + cg, j = 0..31
    float2 acc2[32];
#pragma unroll
    for (int j = 0; j < 32; j++) acc2[j] = make_float2(0.f, 0.f);
#pragma unroll
    for (int kq = 0; kq < 32; kq += 4) {
        float2 qa = q2[kq >> 1], qb = q2[(kq >> 1) + 1];
#pragma unroll
        for (int j = 0; j < 32; j++) {
            int m = (j << 4) + cg;
            float4 kv = *(float4*)&Ks[m * 36 + kq];
            acc2[j] = ffma2(qa, make_float2(kv.x, kv.y), acc2[j]);
            acc2[j] = ffma2(qb, make_float2(kv.z, kv.w), acc2[j]);
        }
    }

    size_t abase = ((size_t)bh * N_ + n) * N_;
    float s[32];
#pragma unroll
    for (int j = 0; j < 32; j++) {
        int m = (j << 4) + cg;
        float sc = (acc2[j].x + acc2[j].y) * RSQRT_DH + attn[abase + m];
        s[j] = (mok[m] != 0.f) ? sc : -1e6f;
    }

    // softmax across half-warp (16 lanes hold the 512-wide row)
    float mx = -3.0e38f;
#pragma unroll
    for (int j = 0; j < 32; j++) mx = fmaxf(mx, s[j]);
#pragma unroll
    for (int o = 8; o > 0; o >>= 1) mx = fmaxf(mx, __shfl_xor_sync(0xffffffffu, mx, o));
    float sum = 0.f;
#pragma unroll
    for (int j = 0; j < 32; j++) { s[j] = __expf(s[j] - mx); sum += s[j]; }
#pragma unroll
    for (int o = 8; o > 0; o >>= 1) sum += __shfl_xor_sync(0xffffffffu, sum, o);
    float inv = 1.0f / sum;
#pragma unroll
    for (int j = 0; j < 32; j++) {
        float pv = s[j] * inv;
        int m = (j << 4) + cg;
        attn[abase + m] = pv;
        Ps[row * PS_STRIDE + m] = pv;
    }
    __syncthreads();

    // P @ V: thread owns (row, d-pair cg) -> out[row][2*cg], [2*cg+1]
    float2 o2 = make_float2(0.f, 0.f);
    const float* prow = &Ps[row * PS_STRIDE];
#pragma unroll
    for (int m4 = 0; m4 < 512; m4 += 4) {
        float4 p4 = *(const float4*)&prow[m4];
        const float* vb = &Vs[m4 * 36 + (cg << 1)];
        o2 = ffma2(make_float2(p4.x, p4.x), *(const float2*)&vb[0],   o2);
        o2 = ffma2(make_float2(p4.y, p4.y), *(const float2*)&vb[36],  o2);
        o2 = ffma2(make_float2(p4.z, p4.z), *(const float2*)&vb[72],  o2);
        o2 = ffma2(make_float2(p4.w, p4.w), *(const float2*)&vb[108], o2);
    }
    int h = bh & 15;
    *(float2*)&g_o[((size_t)(bb * N_ + n)) * D_ + (h << 5) + (cg << 1)] = o2;
}

// ---------------------------------------------------------------------------
// K4: final = (g_o @ Wo), zero masked query rows. Same 128x64 GEMM core.
// ---------------------------------------------------------------------------
__global__ __launch_bounds__(256) void outproj_kernel(
    const float* __restrict__ Wo, const int* __restrict__ mask,
    float* __restrict__ outp) {
    __shared__ __align__(16) float As[2][16][APAD];
    __shared__ __align__(16) float Bs[2][16][64];

    int tid = threadIdx.x;
    int tx = tid & 15, ty = tid >> 4;
    int row0 = blockIdx.y << 7;
    int col0 = blockIdx.x << 6;

    int arow = tid >> 2, akq = (tid & 3) << 2;
    int brow = tid >> 4, bcol = (tid & 15) << 2;

    float2 acc[8][2];
#pragma unroll
    for (int i = 0; i < 8; i++) { acc[i][0] = make_float2(0.f, 0.f); acc[i][1] = make_float2(0.f, 0.f); }

    {
        float4 a0 = *(const float4*)(g_o + (size_t)(row0 + arow) * 512 + akq);
        float4 a1 = *(const float4*)(g_o + (size_t)(row0 + arow + 64) * 512 + akq);
        As[0][akq + 0][arow] = a0.x; As[0][akq + 1][arow] = a0.y;
        As[0][akq + 2][arow] = a0.z; As[0][akq + 3][arow] = a0.w;
        As[0][akq + 0][arow + 64] = a1.x; As[0][akq + 1][arow + 64] = a1.y;
        As[0][akq + 2][arow + 64] = a1.z; As[0][akq + 3][arow + 64] = a1.w;
        *(float4*)&Bs[0][brow][bcol] = *(const float4*)(Wo + (size_t)brow * 512 + col0 + bcol);
    }
    __syncthreads();

    int buf = 0;
    for (int kk = 0; kk < 512; kk += 16) {
        float4 pa0, pa1, pb0;
        bool pf = (kk + 16) < 512;
        if (pf) {
            pa0 = *(const float4*)(g_o + (size_t)(row0 + arow) * 512 + kk + 16 + akq);
            pa1 = *(const float4*)(g_o + (size_t)(row0 + arow + 64) * 512 + kk + 16 + akq);
            pb0 = *(const float4*)(Wo + (size_t)(kk + 16 + brow) * 512 + col0 + bcol);
        }
#pragma unroll
        for (int k2 = 0; k2 < 16; k2++) {
            float4 a0 = *(float4*)&As[buf][k2][ty << 3];
            float4 a1 = *(float4*)&As[buf][k2][(ty << 3) + 4];
            float4 bv = *(float4*)&Bs[buf][k2][tx << 2];
            float2 b01 = make_float2(bv.x, bv.y);
            float2 b23 = make_float2(bv.z, bv.w);
            acc[0][0] = ffma2(make_float2(a0.x, a0.x), b01, acc[0][0]);
            acc[0][1] = ffma2(make_float2(a0.x, a0.x), b23, acc[0][1]);
            acc[1][0] = ffma2(make_float2(a0.y, a0.y), b01, acc[1][0]);
            acc[1][1] = ffma2(make_float2(a0.y, a0.y), b23, acc[1][1]);
            acc[2][0] = ffma2(make_float2(a0.z, a0.z), b01, acc[2][0]);
            acc[2][1] = ffma2(make_float2(a0.z, a0.z), b23, acc[2][1]);
            acc[3][0] = ffma2(make_float2(a0.w, a0.w), b01, acc[3][0]);
            acc[3][1] = ffma2(make_float2(a0.w, a0.w), b23, acc[3][1]);
            acc[4][0] = ffma2(make_float2(a1.x, a1.x), b01, acc[4][0]);
            acc[4][1] = ffma2(make_float2(a1.x, a1.x), b23, acc[4][1]);
            acc[5][0] = ffma2(make_float2(a1.y, a1.y), b01, acc[5][0]);
            acc[5][1] = ffma2(make_float2(a1.y, a1.y), b23, acc[5][1]);
            acc[6][0] = ffma2(make_float2(a1.z, a1.z), b01, acc[6][0]);
            acc[6][1] = ffma2(make_float2(a1.z, a1.z), b23, acc[6][1]);
            acc[7][0] = ffma2(make_float2(a1.w, a1.w), b01, acc[7][0]);
            acc[7][1] = ffma2(make_float2(a1.w, a1.w), b23, acc[7][1]);
        }
        if (pf) {
            int nb = buf ^ 1;
            As[nb][akq + 0][arow] = pa0.x; As[nb][akq + 1][arow] = pa0.y;
            As[nb][akq + 2][arow] = pa0.z; As[nb][akq + 3][arow] = pa0.w;
            As[nb][akq + 0][arow + 64] = pa1.x; As[nb][akq + 1][arow + 64] = pa1.y;
            As[nb][akq + 2][arow + 64] = pa1.z; As[nb][akq + 3][arow + 64] = pa1.w;
            *(float4*)&Bs[nb][brow][bcol] = pb0;
        }
        __syncthreads();
        buf ^= 1;
    }

    int c = col0 + (tx << 2);
#pragma unroll
    for (int i = 0; i < 8; i++) {
        int r = row0 + (ty << 3) + i;
        float msk = mask[r] ? 1.f : 0.f;
        float4 v = make_float4(acc[i][0].x * msk, acc[i][0].y * msk,
                               acc[i][1].x * msk, acc[i][1].y * msk);
        *(float4*)&outp[(size_t)r * 512 + c] = v;
    }
}

// ---------------------------------------------------------------------------
extern "C" void kernel_launch(void* const* d_in, const int* in_sizes, int n_in,
                              void* d_out, int out_size) {
    const float* x    = (const float*)d_in[0];
    const float* pb   = (const float*)d_in[1];
    const float* Wq   = (const float*)d_in[2];
    const float* Wk   = (const float*)d_in[3];
    const float* Wv   = (const float*)d_in[4];
    const float* Wo   = (const float*)d_in[5];
    const float* Wp   = (const float*)d_in[6];
    const int*   mask = (const int*)d_in[7];

    float* out  = (float*)d_out;
    float* attn = out + FINAL_ELEMS;

    static int inited = 0;
    if (!inited) {
        cudaFuncSetAttribute(attn_kernel,
                             cudaFuncAttributeMaxDynamicSharedMemorySize,
                             K3_SMEM_BYTES);
        inited = 1;
    }

    qkv_kernel<<<dim3(24, 16), 256>>>(x, Wq, Wk, Wv);
    bias_kernel<<<B_ * N_, 256>>>(pb, Wp, mask, attn);
    attn_kernel<<<dim3(N_ / 16, B_ * H_), 256, K3_SMEM_BYTES>>>(mask, attn);
    outproj_kernel<<<dim3(8, 16), 256>>>(Wo, mask, out);
}